// round 6
// baseline (speedup 1.0000x reference)
#include <cuda_runtime.h>
#include <cstdint>

// Problem shape (fixed by the dataset)
#define NLAYERS 60
#define NB 2048
#define NC 128
#define NCOLS (NB * NC)   // 262144 columns
#define NPAIRS (NCOLS / 2)

// Exact-op intrinsics: nvcc/ptxas will neither fuse nor split these.
// DO NOT TOUCH — this sequence replicates XLA/LLVM contraction bit-exactly
// (R4: rel_err 1.4e-8). The recursion is chaotic; any change diverges.
#define FMUL(a,b)    __fmul_rn((a),(b))
#define FADD(a,b)    __fadd_rn((a),(b))
#define FSUB(a,b)    __fsub_rn((a),(b))
#define FMA(a,b,c)   __fmaf_rn((a),(b),(c))

// Per-layer inputs for a PAIR of adjacent columns, loaded as float2s.
struct In16 {
    float2 t_d, t_df;        // t for cols (c0, c1)
    float2 d0, d1, d2;       // es_direct  24B: (etd0,erd0)(ead0,etd1)(erd1,ead1)
    float2 f0, f1, f2;       // es_diffuse 24B: same packing
};

__device__ __forceinline__ void load_layer(
    const float* __restrict__ t_direct,
    const float* __restrict__ t_diffuse,
    const float* __restrict__ es_d,
    const float* __restrict__ es_df,
    int l, int p, In16& v)           // p = pair index, columns 2p, 2p+1
{
    size_t off = (size_t)l * NCOLS + (size_t)2 * p;
    v.t_d  = __ldcs(reinterpret_cast<const float2*>(t_direct  + off));
    v.t_df = __ldcs(reinterpret_cast<const float2*>(t_diffuse + off));
    const float2* pd = reinterpret_cast<const float2*>(es_d  + off * 3);
    const float2* pf = reinterpret_cast<const float2*>(es_df + off * 3);
    v.d0 = __ldcs(pd + 0); v.d1 = __ldcs(pd + 1); v.d2 = __ldcs(pd + 2);
    v.f0 = __ldcs(pf + 0); v.f1 = __ldcs(pf + 1); v.f2 = __ldcs(pf + 2);
}

// ===== XLA/LLVM-contracted replica for ONE column (frozen, bit-exact) =====
// inputs: t_d,t_df, e_split_direct(etd,erd,ead), e_split_diffuse(etf,erf,eaf)
// state (in/out): r_b_d, r_b_df, a_b_d, a_b_df
// outputs: o0 = {t_m_d,t_m_df,r_bm_d,r_bm_df}, o1 = {a_tm_d,a_tm_df,a_bm_d,a_bm_df}
__device__ __forceinline__ void propagate_col(
    float t_d, float t_df,
    float e_t_d, float e_r_d, float e_a_d,
    float e_t_df, float e_r_df, float e_a_df,
    float& r_b_d, float& r_b_df, float& a_b_d, float& a_b_df,
    float4& o0, float4& o1)
{
    const float e_d  = FSUB(1.0f, t_d);
    const float e_df = FSUB(1.0f, t_df);

    const float m1  = FMUL(e_df, e_r_df);
    const float m3  = FMUL(t_d,  r_b_d);
    const float m7  = FMUL(e_d,  e_t_d);
    const float m18 = FMUL(e_df, e_t_df);
    const float m20 = FMUL(t_df, r_b_df);

    const float denom = FMA(-m1, r_b_df, 1.0f);
    const float d = __frcp_rn(denom);

    const float s = FADD(t_df, m18);

    // direct
    const float m4  = FMUL(m3, e_df);
    const float m5  = FMUL(m4, e_r_df);
    const float t_m_d = FMA(m5, d, FMUL(m7, d));

    const float a_bm_d = FMA(t_d, a_b_d, FMUL(t_m_d, a_b_df));

    const float m12 = FMUL(m7, r_b_df);
    const float r_bm_d = FMA(m3, d, FMUL(m12, d));

    const float m15 = FMUL(r_bm_d, e_df);
    const float a_tm_d = FMA(e_d, e_a_d, FMUL(m15, e_a_df));

    const float r_m_d = FMA(e_d, e_r_d, FMUL(r_bm_d, s));

    // diffuse
    const float m21 = FMUL(m20, e_df);
    const float m22 = FMUL(m21, e_r_df);
    const float t_m_df = FMA(m22, d, FMUL(m18, d));

    const float a_bm_df = FMA(t_df, a_b_df, FMUL(t_m_df, a_b_df));

    const float m28 = FMUL(m18, r_b_df);
    const float r_bm_df = FMA(m20, d, FMUL(m28, d));

    const float m31 = FMUL(r_bm_df, e_df);
    const float a_tm_df = FMA(e_df, e_a_df, FMUL(m31, e_a_df));

    const float r_m_df = FMA(r_bm_df, s, m1);

    o0 = make_float4(t_m_d,  t_m_df,  r_bm_d,  r_bm_df);
    o1 = make_float4(a_tm_d, a_tm_df, a_bm_d,  a_bm_df);

    r_b_d  = r_m_d;
    r_b_df = r_m_df;
    a_b_d  = a_tm_d;
    a_b_df = a_tm_df;
}

__global__ void __launch_bounds__(256, 4)
upward_prop_kernel(
    const float* __restrict__ t_direct,
    const float* __restrict__ t_diffuse,
    const float* __restrict__ es_d,
    const float* __restrict__ es_df,
    const float* __restrict__ r_bottom_direct,
    const float* __restrict__ r_bottom_diffuse,
    const float* __restrict__ a_bottom_direct,
    const float* __restrict__ a_bottom_diffuse,
    float* __restrict__ out)  // (L, B, C, 8)
{
    int p = blockIdx.x * blockDim.x + threadIdx.x;   // pair index
    if (p >= NPAIRS) return;
    const size_t c0 = (size_t)2 * p;

    // scan state for both columns
    float2 rbd = __ldcs(reinterpret_cast<const float2*>(r_bottom_direct  + c0));
    float2 rbf = __ldcs(reinterpret_cast<const float2*>(r_bottom_diffuse + c0));
    float2 abd = __ldcs(reinterpret_cast<const float2*>(a_bottom_direct  + c0));
    float2 abf = __ldcs(reinterpret_cast<const float2*>(a_bottom_diffuse + c0));

    In16 cur, nxt;
    load_layer(t_direct, t_diffuse, es_d, es_df, 0, p, cur);

    for (int l = 0; l < NLAYERS; ++l) {
        // prefetch next layer (8 x LDG.64 in flight over this layer's math)
        if (l + 1 < NLAYERS)
            load_layer(t_direct, t_diffuse, es_d, es_df, l + 1, p, nxt);

        float4 a0, a1, b0, b1;

        // column 0: es packing (etd,erd)(ead, .)(.,.) / same for diffuse
        propagate_col(cur.t_d.x, cur.t_df.x,
                      cur.d0.x, cur.d0.y, cur.d1.x,
                      cur.f0.x, cur.f0.y, cur.f1.x,
                      rbd.x, rbf.x, abd.x, abf.x, a0, a1);

        // column 1: es packing (., .)(.,etd)(erd,ead)
        propagate_col(cur.t_d.y, cur.t_df.y,
                      cur.d1.y, cur.d2.x, cur.d2.y,
                      cur.f1.y, cur.f2.x, cur.f2.y,
                      rbd.y, rbf.y, abd.y, abf.y, b0, b1);

        // 64B contiguous per thread, 2KB contiguous per warp
        float4* o = reinterpret_cast<float4*>(out + ((size_t)l * NCOLS + c0) * 8);
        __stcs(o + 0, a0);
        __stcs(o + 1, a1);
        __stcs(o + 2, b0);
        __stcs(o + 3, b1);

        cur = nxt;
    }
}

extern "C" void kernel_launch(void* const* d_in, const int* in_sizes, int n_in,
                              void* d_out, int out_size)
{
    const float* t_direct   = (const float*)d_in[0];
    const float* t_diffuse  = (const float*)d_in[1];
    const float* es_d       = (const float*)d_in[2];
    const float* es_df      = (const float*)d_in[3];
    const float* r_b_d      = (const float*)d_in[4];
    const float* r_b_df     = (const float*)d_in[5];
    const float* a_b_d      = (const float*)d_in[6];
    const float* a_b_df     = (const float*)d_in[7];
    float* out = (float*)d_out;

    dim3 block(256);
    dim3 grid((NPAIRS + 255) / 256);
    upward_prop_kernel<<<grid, block>>>(t_direct, t_diffuse, es_d, es_df,
                                        r_b_d, r_b_df, a_b_d, a_b_df, out);
}

// round 8
// speedup vs baseline: 1.1866x; 1.1866x over previous
#include <cuda_runtime.h>
#include <cstdint>

// Problem shape (fixed by the dataset)
#define NLAYERS 60
#define NB 2048
#define NC 128
#define NCOLS (NB * NC)   // 262144 columns

// Exact-op intrinsics: nvcc/ptxas will neither fuse nor split these.
// DO NOT TOUCH — this sequence replicates XLA/LLVM contraction bit-exactly
// (R4: rel_err 1.4e-8). The recursion is chaotic; any change diverges.
#define FMUL(a,b)    __fmul_rn((a),(b))
#define FADD(a,b)    __fadd_rn((a),(b))
#define FSUB(a,b)    __fsub_rn((a),(b))
#define FMA(a,b,c)   __fmaf_rn((a),(b),(c))

struct In8 {
    float t_d, t_df;
    float etd, erd, ead;     // e_split_direct[...,0..2]
    float etf, erf, eaf;     // e_split_diffuse[...,0..2]
};

__device__ __forceinline__ void load_layer(
    const float* __restrict__ t_direct,
    const float* __restrict__ t_diffuse,
    const float* __restrict__ es_d,
    const float* __restrict__ es_df,
    int l, int i, In8& v)
{
    size_t off  = (size_t)l * NCOLS + i;
    v.t_d  = __ldcs(t_direct  + off);
    v.t_df = __ldcs(t_diffuse + off);
    const float* pd = es_d  + off * 3;
    const float* pf = es_df + off * 3;
    v.etd = __ldcs(pd + 0);
    v.erd = __ldcs(pd + 1);
    v.ead = __ldcs(pd + 2);
    v.etf = __ldcs(pf + 0);
    v.erf = __ldcs(pf + 1);
    v.eaf = __ldcs(pf + 2);
}

// Force <=40 regs -> 6 CTAs/SM = 48 warps (was 48 regs -> 5 CTAs = 40 warps).
__global__ void __launch_bounds__(256, 6)
upward_prop_kernel(
    const float* __restrict__ t_direct,
    const float* __restrict__ t_diffuse,
    const float* __restrict__ es_d,
    const float* __restrict__ es_df,
    const float* __restrict__ r_bottom_direct,
    const float* __restrict__ r_bottom_diffuse,
    const float* __restrict__ a_bottom_direct,
    const float* __restrict__ a_bottom_diffuse,
    float* __restrict__ out)  // (L, B, C, 8)
{
    int i = blockIdx.x * blockDim.x + threadIdx.x;
    if (i >= NCOLS) return;

    // scan state
    float r_b_d  = __ldcs(r_bottom_direct  + i);
    float r_b_df = __ldcs(r_bottom_diffuse + i);
    float a_b_d  = __ldcs(a_bottom_direct  + i);
    float a_b_df = __ldcs(a_bottom_diffuse + i);

    In8 cur, nxt;
    load_layer(t_direct, t_diffuse, es_d, es_df, 0, i, cur);

    for (int l = 0; l < NLAYERS; ++l) {
        // prefetch next layer's inputs (loads overlap this layer's math)
        if (l + 1 < NLAYERS)
            load_layer(t_direct, t_diffuse, es_d, es_df, l + 1, i, nxt);

        const float t_d  = cur.t_d,  t_df = cur.t_df;
        const float e_t_d = cur.etd, e_r_d = cur.erd, e_a_d = cur.ead;
        const float e_t_df = cur.etf, e_r_df = cur.erf, e_a_df = cur.eaf;

        // ===== XLA/LLVM-contracted replica (HLO CSE + DAGCombiner FMA rules) =====
        const float e_d  = FSUB(1.0f, t_d);
        const float e_df = FSUB(1.0f, t_df);

        const float m1  = FMUL(e_df, e_r_df);
        const float m3  = FMUL(t_d,  r_b_d);
        const float m7  = FMUL(e_d,  e_t_d);
        const float m18 = FMUL(e_df, e_t_df);
        const float m20 = FMUL(t_df, r_b_df);

        const float denom = FMA(-m1, r_b_df, 1.0f);
        const float d = __frcp_rn(denom);

        const float s = FADD(t_df, m18);

        // ---- direct ----
        const float m4  = FMUL(m3, e_df);
        const float m5  = FMUL(m4, e_r_df);
        const float t_m_d = FMA(m5, d, FMUL(m7, d));

        const float a_bm_d = FMA(t_d, a_b_d, FMUL(t_m_d, a_b_df));

        const float m12 = FMUL(m7, r_b_df);
        const float r_bm_d = FMA(m3, d, FMUL(m12, d));

        const float m15 = FMUL(r_bm_d, e_df);
        const float a_tm_d = FMA(e_d, e_a_d, FMUL(m15, e_a_df));

        const float r_m_d = FMA(e_d, e_r_d, FMUL(r_bm_d, s));

        // ---- diffuse ----
        const float m21 = FMUL(m20, e_df);
        const float m22 = FMUL(m21, e_r_df);
        const float t_m_df = FMA(m22, d, FMUL(m18, d));

        const float a_bm_df = FMA(t_df, a_b_df, FMUL(t_m_df, a_b_df));

        const float m28 = FMUL(m18, r_b_df);
        const float r_bm_df = FMA(m20, d, FMUL(m28, d));

        const float m31 = FMUL(r_bm_df, e_df);
        const float a_tm_df = FMA(e_df, e_a_df, FMUL(m31, e_a_df));

        const float r_m_df = FMA(r_bm_df, s, m1);

        // output: [t_m_d, t_m_df, r_bm_d, r_bm_df, a_tm_d, a_tm_df, a_bm_d, a_bm_df]
        float4* o = reinterpret_cast<float4*>(out + ((size_t)l * NCOLS + i) * 8);
        __stcs(o + 0, make_float4(t_m_d,  t_m_df,  r_bm_d,  r_bm_df));
        __stcs(o + 1, make_float4(a_tm_d, a_tm_df, a_bm_d,  a_bm_df));

        // next state = (r_multi_d, r_multi_df, a_top_multi_d, a_top_multi_df)
        r_b_d  = r_m_d;
        r_b_df = r_m_df;
        a_b_d  = a_tm_d;
        a_b_df = a_tm_df;

        cur = nxt;
    }
}

extern "C" void kernel_launch(void* const* d_in, const int* in_sizes, int n_in,
                              void* d_out, int out_size)
{
    const float* t_direct   = (const float*)d_in[0];
    const float* t_diffuse  = (const float*)d_in[1];
    const float* es_d       = (const float*)d_in[2];
    const float* es_df      = (const float*)d_in[3];
    const float* r_b_d      = (const float*)d_in[4];
    const float* r_b_df     = (const float*)d_in[5];
    const float* a_b_d      = (const float*)d_in[6];
    const float* a_b_df     = (const float*)d_in[7];
    float* out = (float*)d_out;

    dim3 block(256);
    dim3 grid((NCOLS + 255) / 256);
    upward_prop_kernel<<<grid, block>>>(t_direct, t_diffuse, es_d, es_df,
                                        r_b_d, r_b_df, a_b_d, a_b_df, out);
}

// round 9
// speedup vs baseline: 1.2495x; 1.0530x over previous
#include <cuda_runtime.h>
#include <cstdint>

// Problem shape (fixed by the dataset)
#define NLAYERS 60
#define NB 2048
#define NC 128
#define NCOLS (NB * NC)   // 262144 columns

// Exact-op intrinsics: nvcc/ptxas will neither fuse nor split these.
// DO NOT TOUCH — this sequence replicates XLA/LLVM contraction bit-exactly
// (R4: rel_err 1.4e-8). The recursion is chaotic; any change diverges.
#define FMUL(a,b)    __fmul_rn((a),(b))
#define FADD(a,b)    __fadd_rn((a),(b))
#define FSUB(a,b)    __fsub_rn((a),(b))
#define FMA(a,b,c)   __fmaf_rn((a),(b),(c))

// <=40 regs -> 6 CTAs/SM = 48 warps. No explicit prefetch buffer this time:
// the input loads are loop-invariant-addressed (l,i) and independent of the
// output stream (__restrict__), so ptxas pipelines them itself without the
// 8 extra live registers that caused R7's spills.
__global__ void __launch_bounds__(256, 6)
upward_prop_kernel(
    const float* __restrict__ t_direct,
    const float* __restrict__ t_diffuse,
    const float* __restrict__ es_d,
    const float* __restrict__ es_df,
    const float* __restrict__ r_bottom_direct,
    const float* __restrict__ r_bottom_diffuse,
    const float* __restrict__ a_bottom_direct,
    const float* __restrict__ a_bottom_diffuse,
    float* __restrict__ out)  // (L, B, C, 8)
{
    int i = blockIdx.x * blockDim.x + threadIdx.x;
    if (i >= NCOLS) return;

    // scan state
    float r_b_d  = __ldcs(r_bottom_direct  + i);
    float r_b_df = __ldcs(r_bottom_diffuse + i);
    float a_b_d  = __ldcs(a_bottom_direct  + i);
    float a_b_df = __ldcs(a_bottom_diffuse + i);

    #pragma unroll 2
    for (int l = 0; l < NLAYERS; ++l) {
        // loads at top of iteration; ptxas hoists/pipelines across iterations
        const size_t off = (size_t)l * NCOLS + i;
        const float t_d  = __ldcs(t_direct  + off);
        const float t_df = __ldcs(t_diffuse + off);
        const float* pd = es_d  + off * 3;
        const float* pf = es_df + off * 3;
        const float e_t_d  = __ldcs(pd + 0);
        const float e_r_d  = __ldcs(pd + 1);
        const float e_a_d  = __ldcs(pd + 2);
        const float e_t_df = __ldcs(pf + 0);
        const float e_r_df = __ldcs(pf + 1);
        const float e_a_df = __ldcs(pf + 2);

        // ===== XLA/LLVM-contracted replica (HLO CSE + DAGCombiner FMA rules) =====
        const float e_d  = FSUB(1.0f, t_d);
        const float e_df = FSUB(1.0f, t_df);

        const float m1  = FMUL(e_df, e_r_df);
        const float m3  = FMUL(t_d,  r_b_d);
        const float m7  = FMUL(e_d,  e_t_d);
        const float m18 = FMUL(e_df, e_t_df);
        const float m20 = FMUL(t_df, r_b_df);

        const float denom = FMA(-m1, r_b_df, 1.0f);
        const float d = __frcp_rn(denom);

        const float s = FADD(t_df, m18);

        // ---- direct ----
        const float m4  = FMUL(m3, e_df);
        const float m5  = FMUL(m4, e_r_df);
        const float t_m_d = FMA(m5, d, FMUL(m7, d));

        const float a_bm_d = FMA(t_d, a_b_d, FMUL(t_m_d, a_b_df));

        const float m12 = FMUL(m7, r_b_df);
        const float r_bm_d = FMA(m3, d, FMUL(m12, d));

        const float m15 = FMUL(r_bm_d, e_df);
        const float a_tm_d = FMA(e_d, e_a_d, FMUL(m15, e_a_df));

        const float r_m_d = FMA(e_d, e_r_d, FMUL(r_bm_d, s));

        // ---- diffuse ----
        const float m21 = FMUL(m20, e_df);
        const float m22 = FMUL(m21, e_r_df);
        const float t_m_df = FMA(m22, d, FMUL(m18, d));

        const float a_bm_df = FMA(t_df, a_b_df, FMUL(t_m_df, a_b_df));

        const float m28 = FMUL(m18, r_b_df);
        const float r_bm_df = FMA(m20, d, FMUL(m28, d));

        const float m31 = FMUL(r_bm_df, e_df);
        const float a_tm_df = FMA(e_df, e_a_df, FMUL(m31, e_a_df));

        const float r_m_df = FMA(r_bm_df, s, m1);

        // output: [t_m_d, t_m_df, r_bm_d, r_bm_df, a_tm_d, a_tm_df, a_bm_d, a_bm_df]
        float4* o = reinterpret_cast<float4*>(out + off * 8);
        __stcs(o + 0, make_float4(t_m_d,  t_m_df,  r_bm_d,  r_bm_df));
        __stcs(o + 1, make_float4(a_tm_d, a_tm_df, a_bm_d,  a_bm_df));

        // next state = (r_multi_d, r_multi_df, a_top_multi_d, a_top_multi_df)
        r_b_d  = r_m_d;
        r_b_df = r_m_df;
        a_b_d  = a_tm_d;
        a_b_df = a_tm_df;
    }
}

extern "C" void kernel_launch(void* const* d_in, const int* in_sizes, int n_in,
                              void* d_out, int out_size)
{
    const float* t_direct   = (const float*)d_in[0];
    const float* t_diffuse  = (const float*)d_in[1];
    const float* es_d       = (const float*)d_in[2];
    const float* es_df      = (const float*)d_in[3];
    const float* r_b_d      = (const float*)d_in[4];
    const float* r_b_df     = (const float*)d_in[5];
    const float* a_b_d      = (const float*)d_in[6];
    const float* a_b_df     = (const float*)d_in[7];
    float* out = (float*)d_out;

    dim3 block(256);
    dim3 grid((NCOLS + 255) / 256);
    upward_prop_kernel<<<grid, block>>>(t_direct, t_diffuse, es_d, es_df,
                                        r_b_d, r_b_df, a_b_d, a_b_df, out);
}

// round 10
// speedup vs baseline: 1.2610x; 1.0092x over previous
#include <cuda_runtime.h>
#include <cstdint>

// Problem shape (fixed by the dataset)
#define NLAYERS 60
#define NB 2048
#define NC 128
#define NCOLS (NB * NC)   // 262144 columns

// Exact-op intrinsics: nvcc/ptxas will neither fuse nor split these.
// DO NOT TOUCH — this sequence replicates XLA/LLVM contraction bit-exactly
// (R4: rel_err 1.4e-8). The recursion is chaotic; any change diverges.
#define FMUL(a,b)    __fmul_rn((a),(b))
#define FADD(a,b)    __fadd_rn((a),(b))
#define FSUB(a,b)    __fsub_rn((a),(b))
#define FMA(a,b,c)   __fmaf_rn((a),(b),(c))

// 128-thread CTAs, 12 CTAs/SM -> 48 warps/SM with a 42-reg cap (vs 40 at
// (256,6)): same warp budget, +2 regs headroom so ptxas doesn't have to
// squeeze, finer-grained CTA retirement to smooth the tail wave.
__global__ void __launch_bounds__(128, 12)
upward_prop_kernel(
    const float* __restrict__ t_direct,
    const float* __restrict__ t_diffuse,
    const float* __restrict__ es_d,
    const float* __restrict__ es_df,
    const float* __restrict__ r_bottom_direct,
    const float* __restrict__ r_bottom_diffuse,
    const float* __restrict__ a_bottom_direct,
    const float* __restrict__ a_bottom_diffuse,
    float* __restrict__ out)  // (L, B, C, 8)
{
    int i = blockIdx.x * blockDim.x + threadIdx.x;
    if (i >= NCOLS) return;

    // scan state
    float r_b_d  = __ldcs(r_bottom_direct  + i);
    float r_b_df = __ldcs(r_bottom_diffuse + i);
    float a_b_d  = __ldcs(a_bottom_direct  + i);
    float a_b_df = __ldcs(a_bottom_diffuse + i);

    #pragma unroll 2
    for (int l = 0; l < NLAYERS; ++l) {
        // loads at top of iteration; ptxas hoists/pipelines across iterations
        const size_t off = (size_t)l * NCOLS + i;
        const float t_d  = __ldcs(t_direct  + off);
        const float t_df = __ldcs(t_diffuse + off);
        const float* pd = es_d  + off * 3;
        const float* pf = es_df + off * 3;
        const float e_t_d  = __ldcs(pd + 0);
        const float e_r_d  = __ldcs(pd + 1);
        const float e_a_d  = __ldcs(pd + 2);
        const float e_t_df = __ldcs(pf + 0);
        const float e_r_df = __ldcs(pf + 1);
        const float e_a_df = __ldcs(pf + 2);

        // ===== XLA/LLVM-contracted replica (HLO CSE + DAGCombiner FMA rules) =====
        const float e_d  = FSUB(1.0f, t_d);
        const float e_df = FSUB(1.0f, t_df);

        const float m1  = FMUL(e_df, e_r_df);
        const float m3  = FMUL(t_d,  r_b_d);
        const float m7  = FMUL(e_d,  e_t_d);
        const float m18 = FMUL(e_df, e_t_df);
        const float m20 = FMUL(t_df, r_b_df);

        const float denom = FMA(-m1, r_b_df, 1.0f);
        const float d = __frcp_rn(denom);

        const float s = FADD(t_df, m18);

        // ---- direct ----
        const float m4  = FMUL(m3, e_df);
        const float m5  = FMUL(m4, e_r_df);
        const float t_m_d = FMA(m5, d, FMUL(m7, d));

        const float a_bm_d = FMA(t_d, a_b_d, FMUL(t_m_d, a_b_df));

        const float m12 = FMUL(m7, r_b_df);
        const float r_bm_d = FMA(m3, d, FMUL(m12, d));

        const float m15 = FMUL(r_bm_d, e_df);
        const float a_tm_d = FMA(e_d, e_a_d, FMUL(m15, e_a_df));

        const float r_m_d = FMA(e_d, e_r_d, FMUL(r_bm_d, s));

        // ---- diffuse ----
        const float m21 = FMUL(m20, e_df);
        const float m22 = FMUL(m21, e_r_df);
        const float t_m_df = FMA(m22, d, FMUL(m18, d));

        const float a_bm_df = FMA(t_df, a_b_df, FMUL(t_m_df, a_b_df));

        const float m28 = FMUL(m18, r_b_df);
        const float r_bm_df = FMA(m20, d, FMUL(m28, d));

        const float m31 = FMUL(r_bm_df, e_df);
        const float a_tm_df = FMA(e_df, e_a_df, FMUL(m31, e_a_df));

        const float r_m_df = FMA(r_bm_df, s, m1);

        // output: [t_m_d, t_m_df, r_bm_d, r_bm_df, a_tm_d, a_tm_df, a_bm_d, a_bm_df]
        float4* o = reinterpret_cast<float4*>(out + off * 8);
        __stcs(o + 0, make_float4(t_m_d,  t_m_df,  r_bm_d,  r_bm_df));
        __stcs(o + 1, make_float4(a_tm_d, a_tm_df, a_bm_d,  a_bm_df));

        // next state = (r_multi_d, r_multi_df, a_top_multi_d, a_top_multi_df)
        r_b_d  = r_m_d;
        r_b_df = r_m_df;
        a_b_d  = a_tm_d;
        a_b_df = a_tm_df;
    }
}

extern "C" void kernel_launch(void* const* d_in, const int* in_sizes, int n_in,
                              void* d_out, int out_size)
{
    const float* t_direct   = (const float*)d_in[0];
    const float* t_diffuse  = (const float*)d_in[1];
    const float* es_d       = (const float*)d_in[2];
    const float* es_df      = (const float*)d_in[3];
    const float* r_b_d      = (const float*)d_in[4];
    const float* r_b_df     = (const float*)d_in[5];
    const float* a_b_d      = (const float*)d_in[6];
    const float* a_b_df     = (const float*)d_in[7];
    float* out = (float*)d_out;

    dim3 block(128);
    dim3 grid((NCOLS + 127) / 128);
    upward_prop_kernel<<<grid, block>>>(t_direct, t_diffuse, es_d, es_df,
                                        r_b_d, r_b_df, a_b_d, a_b_df, out);
}